// round 10
// baseline (speedup 1.0000x reference)
#include <cuda_runtime.h>
#include <cstdint>
#include <cstddef>

#define Bn 256
#define Tn 2048
#define Nn 17
#define En 8
#define An 4
#define Mn 2
#define Hn 768
#define FULL 0xffffffffu
#define SEG 408   // segments: [0..407][408..815][816..1223][1224..1631][1632..2047]

__device__ float g_trans[Nn * Nn];
__device__ float g_E[Nn * Nn];
__device__ float g_scratch[Bn];
__device__ int g_done;

// ---------------------------------------------------------------------------
// Kernel 1: build transition matrix (17x17) and its elementwise exp.
// ---------------------------------------------------------------------------
__global__ void k_build(const float* __restrict__ hiddens,
                        const float* __restrict__ p_in,
                        const float* __restrict__ p_cross,
                        const float* __restrict__ p_out,
                        const float* __restrict__ p_to_out,
                        const float* __restrict__ p_from_out,
                        const float* __restrict__ w_attn,
                        const float* __restrict__ b_attn) {
    __shared__ float att[En][An];
    int tid = threadIdx.x;
    int wid = tid >> 5, lane = tid & 31;
    if (tid == 0) g_done = 0;
    if (wid < En * An) {
        int e = wid / An, a = wid % An;
        float s = 0.f;
        for (int h = lane; h < Hn; h += 32)
            s = fmaf(hiddens[e * Hn + h], w_attn[h * An + a], s);
#pragma unroll
        for (int off = 16; off; off >>= 1) s += __shfl_xor_sync(FULL, s, off);
        if (lane == 0) att[e][a] = s + b_attn[a];
    }
    __syncthreads();
    if (tid < An) {
        int a = tid;
        float col[En], mx = -3.4e38f;
        for (int e = 0; e < En; e++) { col[e] = att[e][a]; mx = fmaxf(mx, col[e]); }
        float sm = 0.f;
        for (int e = 0; e < En; e++) { col[e] = expf(col[e] - mx); sm += col[e]; }
        for (int e = 0; e < En; e++) att[e][a] = col[e] / sm;
    }
    __syncthreads();
    if (tid < En) {
        int e = tid;
        float row[An], mx = -3.4e38f;
        for (int a = 0; a < An; a++) { row[a] = att[e][a] * 10.f; mx = fmaxf(mx, row[a]); }
        float sm = 0.f;
        for (int a = 0; a < An; a++) { row[a] = expf(row[a] - mx); sm += row[a]; }
        for (int a = 0; a < An; a++) att[e][a] = row[a] / sm;
    }
    __syncthreads();
    if (tid < Nn * Nn) {
        int r = tid / Nn, c = tid % Nn;
        float v;
        if (r == 0 && c == 0) {
            v = p_out[0];
        } else if (r == 0) {
            v = p_from_out[(c - 1) % Mn];
        } else if (c == 0) {
            v = p_to_out[(r - 1) % Mn];
        } else {
            int e = (r - 1) / Mn, m = (r - 1) % Mn;
            int f = (c - 1) / Mn, mp = (c - 1) % Mn;
            if (e == f) {
                float s2 = 0.f;
                for (int a = 0; a < An; a++)
                    s2 = fmaf(p_in[a * Mn * Mn + m * Mn + mp], att[e][a], s2);
                v = s2 * (1.0f / An);
            } else {
                v = p_cross[m * Mn + mp];
            }
        }
        g_trans[tid] = v;
        g_E[tid] = expf(v);
    }
}

// ---------------------------------------------------------------------------
// Kernel 2: 5 warps per batch. Warp w (0-3) runs TWO interleaved chains:
//  forward a over segment w+1 and backward b over segment w+2 (rank-1
//  interior summaries, same telescoped combine as before). One __syncwarp
//  per double-step serves both ping-pong buffers. Warp 4: numerator.
// ---------------------------------------------------------------------------
__global__ void __launch_bounds__(160, 2)
k_scan(const float* __restrict__ inputs,
       const int* __restrict__ tags,
       const int* __restrict__ mask,
       float* __restrict__ out) {
    int b = blockIdx.x;
    int wid = threadIdx.x >> 5;
    int j = threadIdx.x & 31;
    bool act = (j < Nn);

    __shared__ float s_tr[Nn * Nn];
    __shared__ __align__(16) float wb[8][2][20];
    __shared__ __align__(16) float s_vec[8][20];
    __shared__ double s_l2[8];
    __shared__ float s_s0, s_num;

    for (int idx = threadIdx.x; idx < Nn * Nn; idx += 160) s_tr[idx] = g_trans[idx];
    __syncthreads();

    const float* inp = inputs + (size_t)b * Tn * Nn;
    const int* tgp = tags + (size_t)b * Tn;
    const int* mkp = mask + (size_t)b * Tn;

    if (wid < 4) {
        int cw = wid;
        int tb0 = cw * SEG;                            // fwd segment start
        int thi = (cw == 3) ? 2047 : (815 + cw * SEG); // bwd segment top

        float E0  = act ? g_E[0 * Nn + j]  : 0.f, E1  = act ? g_E[1 * Nn + j]  : 0.f;
        float E2  = act ? g_E[2 * Nn + j]  : 0.f, E3  = act ? g_E[3 * Nn + j]  : 0.f;
        float E4  = act ? g_E[4 * Nn + j]  : 0.f, E5  = act ? g_E[5 * Nn + j]  : 0.f;
        float E6  = act ? g_E[6 * Nn + j]  : 0.f, E7  = act ? g_E[7 * Nn + j]  : 0.f;
        float E8  = act ? g_E[8 * Nn + j]  : 0.f, E9  = act ? g_E[9 * Nn + j]  : 0.f;
        float E10 = act ? g_E[10 * Nn + j] : 0.f, E11 = act ? g_E[11 * Nn + j] : 0.f;
        float E12 = act ? g_E[12 * Nn + j] : 0.f, E13 = act ? g_E[13 * Nn + j] : 0.f;
        float E14 = act ? g_E[14 * Nn + j] : 0.f, E15 = act ? g_E[15 * Nn + j] : 0.f;
        float E16 = act ? g_E[16 * Nn + j] : 0.f;
        float F0  = act ? g_E[j * Nn + 0]  : 0.f, F1  = act ? g_E[j * Nn + 1]  : 0.f;
        float F2  = act ? g_E[j * Nn + 2]  : 0.f, F3  = act ? g_E[j * Nn + 3]  : 0.f;
        float F4  = act ? g_E[j * Nn + 4]  : 0.f, F5  = act ? g_E[j * Nn + 5]  : 0.f;
        float F6  = act ? g_E[j * Nn + 6]  : 0.f, F7  = act ? g_E[j * Nn + 7]  : 0.f;
        float F8  = act ? g_E[j * Nn + 8]  : 0.f, F9  = act ? g_E[j * Nn + 9]  : 0.f;
        float F10 = act ? g_E[j * Nn + 10] : 0.f, F11 = act ? g_E[j * Nn + 11] : 0.f;
        float F12 = act ? g_E[j * Nn + 12] : 0.f, F13 = act ? g_E[j * Nn + 13] : 0.f;
        float F14 = act ? g_E[j * Nn + 14] : 0.f, F15 = act ? g_E[j * Nn + 15] : 0.f;
        float F16 = act ? g_E[j * Nn + 16] : 0.f;

        float fA[8], fB[8], bA[8], bB[8];
        int mfA[8], mfB[8], mbA[8], mbB[8];
        float ewf[8], ewb[8];

        int tbF = tb0;
        int tbB = thi - 7;
#pragma unroll
        for (int u = 0; u < 8; u++) {
            fA[u] = act ? __ldg(inp + (size_t)(tbF + u) * Nn + j) : 0.f;
            mfA[u] = __ldg(mkp + tbF + u);
            bA[u] = act ? __ldg(inp + (size_t)(tbB + u) * Nn + j) : 0.f;
            mbA[u] = __ldg(mkp + tbB + u);
        }

        float w, s0 = 0.f;
        double l2f = 0.0, l2b = 0.0;
        if (cw == 0) {          // true init: alpha0 = emit(t=0)
            float r0 = fA[0];
            s0 = __shfl_sync(FULL, r0, 0);
            w = act ? __expf(r0 - s0) : 0.f;
        } else {
            w = act ? 1.f : 0.f;
        }
        if (act) { wb[cw][0][j] = w; wb[cw][1][j] = w; }
        float ur = act ? 1.f : 0.f;

        // ---- peel: bwd seg 5 has 52 blocks, others 51; run one bwd-only ----
        if (cw == 3) {
            int tp = tbB - 8;
#pragma unroll
            for (int u = 0; u < 8; u++) {
                bB[u] = act ? __ldg(inp + (size_t)(tp + u) * Nn + j) : 0.f;
                mbB[u] = __ldg(mkp + tp + u);
                ewb[u] = __expf(bA[u]);
            }
#pragma unroll
            for (int u = 0; u < 8; u++) {
                int ub = 7 - u;
                float z = ewb[ub] * ur;
                if (act) wb[4 + cw][ub & 1][j] = z;
                __syncwarp();
                float4 q0 = *(const float4*)&wb[4 + cw][ub & 1][0];
                float4 q1 = *(const float4*)&wb[4 + cw][ub & 1][4];
                float4 q2 = *(const float4*)&wb[4 + cw][ub & 1][8];
                float4 q3 = *(const float4*)&wb[4 + cw][ub & 1][12];
                float q16 = wb[4 + cw][ub & 1][16];
                float c0 = q0.x * F0, c1 = q0.y * F1, c2 = q0.z * F2, c3 = q0.w * F3;
                float c4 = q1.x * F4, c5 = q1.y * F5, c6 = q1.z * F6, c7 = q1.w * F7;
                c0 = fmaf(q2.x, F8, c0);  c1 = fmaf(q2.y, F9, c1);
                c2 = fmaf(q2.z, F10, c2); c3 = fmaf(q2.w, F11, c3);
                c4 = fmaf(q3.x, F12, c4); c5 = fmaf(q3.y, F13, c5);
                c6 = fmaf(q3.z, F14, c6); c7 = fmaf(q3.w, F15, c7);
                c0 = fmaf(q16, F16, c0);
                float cand = ((c0 + c1) + (c2 + c3)) + ((c4 + c5) + (c6 + c7));
                ur = (mbA[ub] > 0) ? cand : ur;
                if (ub == 0) {
                    float sc = q0.x;
                    ur *= __frcp_rn(sc);
                    l2b += (double)__log2f(sc);
                }
            }
#pragma unroll
            for (int u = 0; u < 8; u++) { bA[u] = bB[u]; mbA[u] = mbB[u]; }
            tbB -= 8;
        }

        // ---- main: 51 paired blocks (fwd ascending, bwd descending) ----
        for (int blk = 0; blk < 51; blk++) {
            int tpf = tbF + 8, tpb = tbB - 8;   // prefetch (in-bounds even on last iter)
#pragma unroll
            for (int u = 0; u < 8; u++) {
                fB[u] = act ? __ldg(inp + (size_t)(tpf + u) * Nn + j) : 0.f;
                mfB[u] = __ldg(mkp + tpf + u);
                bB[u] = act ? __ldg(inp + (size_t)(tpb + u) * Nn + j) : 0.f;
                mbB[u] = __ldg(mkp + tpb + u);
            }
#pragma unroll
            for (int u = 0; u < 8; u++) { ewf[u] = __expf(fA[u]); ewb[u] = __expf(bA[u]); }
#pragma unroll
            for (int u = 0; u < 8; u++) {
                int ub = 7 - u;
                // backward: store z before the shared sync
                float z = ewb[ub] * ur;
                if (act) wb[4 + cw][ub & 1][j] = z;
                __syncwarp();
                // forward step (skip t=0 for cw==0, handled in init)
                if (!(u == 0) || !(cw == 0 && blk == 0)) {
                    float4 v0 = *(const float4*)&wb[cw][(u + 1) & 1][0];
                    float4 v1 = *(const float4*)&wb[cw][(u + 1) & 1][4];
                    float4 v2 = *(const float4*)&wb[cw][(u + 1) & 1][8];
                    float4 v3 = *(const float4*)&wb[cw][(u + 1) & 1][12];
                    float v16 = wb[cw][(u + 1) & 1][16];
                    float a0 = v0.x * E0, a1 = v0.y * E1, a2 = v0.z * E2, a3 = v0.w * E3;
                    float a4 = v1.x * E4, a5 = v1.y * E5, a6 = v1.z * E6, a7 = v1.w * E7;
                    a0 = fmaf(v2.x, E8, a0);  a1 = fmaf(v2.y, E9, a1);
                    a2 = fmaf(v2.z, E10, a2); a3 = fmaf(v2.w, E11, a3);
                    a4 = fmaf(v3.x, E12, a4); a5 = fmaf(v3.y, E13, a5);
                    a6 = fmaf(v3.z, E14, a6); a7 = fmaf(v3.w, E15, a7);
                    a0 = fmaf(v16, E16, a0);
                    float wn = ewf[u] * (((a0 + a1) + (a2 + a3)) + ((a4 + a5) + (a6 + a7)));
                    w = (mfA[u] > 0) ? wn : w;
                    if (u == 7) {           // free renorm via prev step's w[0]
                        float sc = v0.x;
                        w *= __frcp_rn(sc);
                        l2f += (double)__log2f(sc);
                    }
                    if (act) wb[cw][u & 1][j] = w;
                }
                // backward step (read z vector just published)
                {
                    float4 q0 = *(const float4*)&wb[4 + cw][ub & 1][0];
                    float4 q1 = *(const float4*)&wb[4 + cw][ub & 1][4];
                    float4 q2 = *(const float4*)&wb[4 + cw][ub & 1][8];
                    float4 q3 = *(const float4*)&wb[4 + cw][ub & 1][12];
                    float q16 = wb[4 + cw][ub & 1][16];
                    float c0 = q0.x * F0, c1 = q0.y * F1, c2 = q0.z * F2, c3 = q0.w * F3;
                    float c4 = q1.x * F4, c5 = q1.y * F5, c6 = q1.z * F6, c7 = q1.w * F7;
                    c0 = fmaf(q2.x, F8, c0);  c1 = fmaf(q2.y, F9, c1);
                    c2 = fmaf(q2.z, F10, c2); c3 = fmaf(q2.w, F11, c3);
                    c4 = fmaf(q3.x, F12, c4); c5 = fmaf(q3.y, F13, c5);
                    c6 = fmaf(q3.z, F14, c6); c7 = fmaf(q3.w, F15, c7);
                    c0 = fmaf(q16, F16, c0);
                    float cand = ((c0 + c1) + (c2 + c3)) + ((c4 + c5) + (c6 + c7));
                    ur = (mbA[ub] > 0) ? cand : ur;
                    if (ub == 0) {
                        float sc = q0.x;
                        ur *= __frcp_rn(sc);
                        l2b += (double)__log2f(sc);
                    }
                }
            }
#pragma unroll
            for (int u = 0; u < 8; u++) {
                fA[u] = fB[u]; mfA[u] = mfB[u];
                bA[u] = bB[u]; mbA[u] = mbB[u];
            }
            tbF += 8; tbB -= 8;
        }
        if (act) { s_vec[cw][j] = w; s_vec[4 + cw][j] = ur; }
        if (j == 0) { s_l2[cw] = l2f; s_l2[4 + cw] = l2b; if (cw == 0) s_s0 = s0; }
    } else {
        // ===================== NUMERATOR =====================
        float tr_acc = 0.f, em_acc = 0.f;
        int cnt = 0;
        for (int t = j; t < Tn - 1; t += 32) {
            int tg0 = __ldg(tgp + t), tg1 = __ldg(tgp + t + 1);
            int mk0 = __ldg(mkp + t), mk1 = __ldg(mkp + t + 1);
            float ev = __ldg(inp + (size_t)t * Nn + tg0);
            tr_acc = fmaf(s_tr[tg0 * Nn + tg1], (float)mk1, tr_acc);
            em_acc = fmaf(ev, (float)mk0, em_acc);
            cnt += mk0;
        }
#pragma unroll
        for (int off = 16; off; off >>= 1) {
            tr_acc += __shfl_xor_sync(FULL, tr_acc, off);
            em_acc += __shfl_xor_sync(FULL, em_acc, off);
            cnt += __shfl_xor_sync(FULL, cnt, off);
        }
        if (j == 0) {
            int mkL = __ldg(mkp + Tn - 1);
            cnt += mkL;
            int li = cnt - 1; if (li < 0) li = 0;
            int tagL = __ldg(tgp + li);
            float evL = __ldg(inp + (size_t)(Tn - 1) * Nn + tagL) * (float)mkL;
            s_num = tr_acc + em_acc + evL;
        }
    }
    __syncthreads();

    if (wid == 0) {
        // ---- combine: telescoped rank-1 product ----
        float d1 = act ? s_vec[4][j] * s_vec[0][j] : 0.f;   // b2.a1
        float d2 = act ? s_vec[5][j] * s_vec[1][j] : 0.f;   // b3.a2
        float d3 = act ? s_vec[6][j] * s_vec[2][j] : 0.f;   // b4.a3
        float d4 = act ? s_vec[7][j] * s_vec[3][j] : 0.f;   // b5.a4
        float m2 = act ? s_vec[1][j] : 0.f;                  // sum a2
        float m3 = act ? s_vec[2][j] : 0.f;
        float m4 = act ? s_vec[3][j] : 0.f;
#pragma unroll
        for (int off = 16; off; off >>= 1) {
            d1 += __shfl_xor_sync(FULL, d1, off);
            d2 += __shfl_xor_sync(FULL, d2, off);
            d3 += __shfl_xor_sync(FULL, d3, off);
            d4 += __shfl_xor_sync(FULL, d4, off);
            m2 += __shfl_xor_sync(FULL, m2, off);
            m3 += __shfl_xor_sync(FULL, m3, off);
            m4 += __shfl_xor_sync(FULL, m4, off);
        }
        if (j == 0) {
            // scales of a2..a4 cancel between d_s and m_s; only La1 + backward
            // scales survive.
            double l2t = s_l2[0] + s_l2[4] + s_l2[5] + s_l2[6] + s_l2[7];
            double den = (double)s_s0 + 0.6931471805599453 * l2t
                       + log((double)d1) + log((double)d2)
                       + log((double)d3) + log((double)d4)
                       - log((double)m2) - log((double)m3) - log((double)m4);
            g_scratch[b] = (float)((double)s_num - den);
            __threadfence();
        }
        int flag = 0;
        if (j == 0) {
            int ticket = atomicAdd(&g_done, 1);
            flag = (ticket == Bn - 1);
        }
        flag = __shfl_sync(FULL, flag, 0);
        if (flag) {
            __threadfence();
            volatile float* gs = g_scratch;
            double acc = 0.0;
#pragma unroll
            for (int k = 0; k < Bn / 32; k++) acc += (double)gs[j + k * 32];
#pragma unroll
            for (int off = 16; off; off >>= 1) acc += __shfl_xor_sync(FULL, acc, off);
            if (j == 0) out[0] = (float)acc;
        }
    }
}

extern "C" void kernel_launch(void* const* d_in, const int* in_sizes, int n_in,
                              void* d_out, int out_size) {
    const float* inputs     = (const float*)d_in[0];
    const int*   tags       = (const int*)d_in[1];
    const float* hiddens    = (const float*)d_in[2];
    const int*   mask       = (const int*)d_in[3];
    const float* p_in       = (const float*)d_in[4];
    const float* p_cross    = (const float*)d_in[5];
    const float* p_out      = (const float*)d_in[6];
    const float* p_to_out   = (const float*)d_in[7];
    const float* p_from_out = (const float*)d_in[8];
    const float* w_attn     = (const float*)d_in[9];
    const float* b_attn     = (const float*)d_in[10];

    k_build<<<1, 1024>>>(hiddens, p_in, p_cross, p_out, p_to_out, p_from_out,
                         w_attn, b_attn);
    k_scan<<<Bn, 160>>>(inputs, tags, mask, (float*)d_out);
}

// round 11
// speedup vs baseline: 1.1380x; 1.1380x over previous
#include <cuda_runtime.h>
#include <cstdint>
#include <cstddef>

#define Bn 256
#define Tn 2048
#define Nn 17
#define En 8
#define An 4
#define Mn 2
#define Hn 768
#define FULL 0xffffffffu
// 3 time-segments (transition index space t=1..2047):
//  seg1: t in [1..679]   (fwd chain, true init at t=0)
//  seg2: t in [680..1359] (fwd probe a2 + bwd probe b2)
//  seg3: t in [1360..2047] (bwd probe b3)
// den = s0 + ln2(La1+Lb2+Lb3) + ln(b2.a1) + ln(b3.a2) - ln(sum a2)

__device__ float g_trans[Nn * Nn];
__device__ float g_E[Nn * Nn];
__device__ float g_scratch[Bn];
__device__ int g_done;

// ---------------------------------------------------------------------------
// Kernel 1: build transition matrix (17x17) and its elementwise exp.
// ---------------------------------------------------------------------------
__global__ void k_build(const float* __restrict__ hiddens,
                        const float* __restrict__ p_in,
                        const float* __restrict__ p_cross,
                        const float* __restrict__ p_out,
                        const float* __restrict__ p_to_out,
                        const float* __restrict__ p_from_out,
                        const float* __restrict__ w_attn,
                        const float* __restrict__ b_attn) {
    __shared__ float att[En][An];
    int tid = threadIdx.x;
    int wid = tid >> 5, lane = tid & 31;
    if (tid == 0) g_done = 0;
    if (wid < En * An) {
        int e = wid / An, a = wid % An;
        float s = 0.f;
        for (int h = lane; h < Hn; h += 32)
            s = fmaf(hiddens[e * Hn + h], w_attn[h * An + a], s);
#pragma unroll
        for (int off = 16; off; off >>= 1) s += __shfl_xor_sync(FULL, s, off);
        if (lane == 0) att[e][a] = s + b_attn[a];
    }
    __syncthreads();
    if (tid < An) {
        int a = tid;
        float col[En], mx = -3.4e38f;
        for (int e = 0; e < En; e++) { col[e] = att[e][a]; mx = fmaxf(mx, col[e]); }
        float sm = 0.f;
        for (int e = 0; e < En; e++) { col[e] = expf(col[e] - mx); sm += col[e]; }
        for (int e = 0; e < En; e++) att[e][a] = col[e] / sm;
    }
    __syncthreads();
    if (tid < En) {
        int e = tid;
        float row[An], mx = -3.4e38f;
        for (int a = 0; a < An; a++) { row[a] = att[e][a] * 10.f; mx = fmaxf(mx, row[a]); }
        float sm = 0.f;
        for (int a = 0; a < An; a++) { row[a] = expf(row[a] - mx); sm += row[a]; }
        for (int a = 0; a < An; a++) att[e][a] = row[a] / sm;
    }
    __syncthreads();
    if (tid < Nn * Nn) {
        int r = tid / Nn, c = tid % Nn;
        float v;
        if (r == 0 && c == 0) {
            v = p_out[0];
        } else if (r == 0) {
            v = p_from_out[(c - 1) % Mn];
        } else if (c == 0) {
            v = p_to_out[(r - 1) % Mn];
        } else {
            int e = (r - 1) / Mn, m = (r - 1) % Mn;
            int f = (c - 1) / Mn, mp = (c - 1) % Mn;
            if (e == f) {
                float s2 = 0.f;
                for (int a = 0; a < An; a++)
                    s2 = fmaf(p_in[a * Mn * Mn + m * Mn + mp], att[e][a], s2);
                v = s2 * (1.0f / An);
            } else {
                v = p_cross[m * Mn + mp];
            }
        }
        g_trans[tid] = v;
        g_E[tid] = expf(v);
    }
}

// ---------------------------------------------------------------------------
// Kernel 2: 5 warps per batch (3-segment rank-1 decomposition):
//  w0: fwd a1 over seg1 (true init)   w1: fwd a2 over seg2 (probe ones)
//  w2: bwd b2 over seg2 (probe ones)  w3: bwd b3 over seg3 (probe ones)
//  w4: numerator.
// ---------------------------------------------------------------------------
__global__ void __launch_bounds__(160, 2)
k_scan(const float* __restrict__ inputs,
       const int* __restrict__ tags,
       const int* __restrict__ mask,
       float* __restrict__ out) {
    int b = blockIdx.x;
    int wid = threadIdx.x >> 5;
    int j = threadIdx.x & 31;
    bool act = (j < Nn);

    __shared__ float s_tr[Nn * Nn];
    __shared__ __align__(16) float wb[4][2][20];
    __shared__ __align__(16) float s_vec[4][20];   // 0=a1, 1=a2, 2=b2, 3=b3
    __shared__ double s_l2[4];
    __shared__ float s_s0, s_num;

    for (int idx = threadIdx.x; idx < Nn * Nn; idx += 160) s_tr[idx] = g_trans[idx];
    __syncthreads();

    const float* inp = inputs + (size_t)b * Tn * Nn;
    const int* tgp = tags + (size_t)b * Tn;
    const int* mkp = mask + (size_t)b * Tn;

    if (wid < 2) {
        // ============ FORWARD chain: cw=0 seg1 [t=0..679], cw=1 seg2 [680..1359]
        int cw = wid;
        int tb0 = (cw == 0) ? 0 : 680;
        const int NBLK = 85;
        float E0  = act ? g_E[0 * Nn + j]  : 0.f, E1  = act ? g_E[1 * Nn + j]  : 0.f;
        float E2  = act ? g_E[2 * Nn + j]  : 0.f, E3  = act ? g_E[3 * Nn + j]  : 0.f;
        float E4  = act ? g_E[4 * Nn + j]  : 0.f, E5  = act ? g_E[5 * Nn + j]  : 0.f;
        float E6  = act ? g_E[6 * Nn + j]  : 0.f, E7  = act ? g_E[7 * Nn + j]  : 0.f;
        float E8  = act ? g_E[8 * Nn + j]  : 0.f, E9  = act ? g_E[9 * Nn + j]  : 0.f;
        float E10 = act ? g_E[10 * Nn + j] : 0.f, E11 = act ? g_E[11 * Nn + j] : 0.f;
        float E12 = act ? g_E[12 * Nn + j] : 0.f, E13 = act ? g_E[13 * Nn + j] : 0.f;
        float E14 = act ? g_E[14 * Nn + j] : 0.f, E15 = act ? g_E[15 * Nn + j] : 0.f;
        float E16 = act ? g_E[16 * Nn + j] : 0.f;

        float rA[8], rB[8], rC[8];
        int mA[8], mB[8], mC[8];
        float ew[8];
#pragma unroll
        for (int u = 0; u < 8; u++) {
            rA[u] = act ? __ldg(inp + (size_t)(tb0 + u) * Nn + j) : 0.f;
            mA[u] = __ldg(mkp + tb0 + u);
            rB[u] = act ? __ldg(inp + (size_t)(tb0 + 8 + u) * Nn + j) : 0.f;
            mB[u] = __ldg(mkp + tb0 + 8 + u);
            rC[u] = 0.f; mC[u] = 0;
        }
#pragma unroll
        for (int u = 0; u < 8; u++) ew[u] = __expf(rA[u]);

        float w, s0 = 0.f;
        double l2 = 0.0;
        if (cw == 0) {      // true init: alpha0 = emit(t=0)
            float r0v = rA[0];
            s0 = __shfl_sync(FULL, r0v, 0);
            w = act ? __expf(r0v - s0) : 0.f;
        } else {            // rank-1 probe from ones
            w = act ? 1.f : 0.f;
        }
        // init both ping-pong slots (first executed step reads slot (u+1)&1)
        if (act) { wb[cw][0][j] = w; wb[cw][1][j] = w; }

        for (int blk = 0; blk < NBLK; blk++) {
            if (blk + 2 < NBLK) {
                int tp = tb0 + (blk + 2) * 8;
#pragma unroll
                for (int u = 0; u < 8; u++) {
                    rC[u] = act ? __ldg(inp + (size_t)(tp + u) * Nn + j) : 0.f;
                    mC[u] = __ldg(mkp + tp + u);
                }
            }
#pragma unroll
            for (int u = 0; u < 8; u++) {
                if (cw == 0 && blk == 0 && u == 0) continue;   // t=0 in init
                __syncwarp();
                float4 v0 = *(const float4*)&wb[cw][(u + 1) & 1][0];
                float4 v1 = *(const float4*)&wb[cw][(u + 1) & 1][4];
                float4 v2 = *(const float4*)&wb[cw][(u + 1) & 1][8];
                float4 v3 = *(const float4*)&wb[cw][(u + 1) & 1][12];
                float v16 = wb[cw][(u + 1) & 1][16];
                float a0 = v0.x * E0, a1 = v0.y * E1, a2 = v0.z * E2, a3 = v0.w * E3;
                float a4 = v1.x * E4, a5 = v1.y * E5, a6 = v1.z * E6, a7 = v1.w * E7;
                a0 = fmaf(v2.x, E8, a0);  a1 = fmaf(v2.y, E9, a1);
                a2 = fmaf(v2.z, E10, a2); a3 = fmaf(v2.w, E11, a3);
                a4 = fmaf(v3.x, E12, a4); a5 = fmaf(v3.y, E13, a5);
                a6 = fmaf(v3.z, E14, a6); a7 = fmaf(v3.w, E15, a7);
                a0 = fmaf(v16, E16, a0);
                float wn = ew[u] * (((a0 + a1) + (a2 + a3)) + ((a4 + a5) + (a6 + a7)));
                w = (mA[u] > 0) ? wn : w;
                if (u == 7) {            // free renorm via prev step's w[0]
                    float sc = v0.x;
                    w *= __frcp_rn(sc);
                    l2 += (double)__log2f(sc);
                }
                if (act) wb[cw][u & 1][j] = w;
            }
#pragma unroll
            for (int u = 0; u < 8; u++) {
                ew[u] = __expf(rB[u]);
                rA[u] = rB[u]; mA[u] = mB[u];
                rB[u] = rC[u]; mB[u] = mC[u];
            }
        }
        if (act) s_vec[cw][j] = w;
        if (j == 0) { s_l2[cw] = l2; if (cw == 0) s_s0 = s0; }
    } else if (wid < 4) {
        // ============ BACKWARD chain: cw=2 seg2 [1359..680], cw=3 seg3 [2047..1360]
        int cw = wid;
        int thi = (cw == 2) ? 1359 : 2047;
        int tlo = (cw == 2) ? 680 : 1360;
        int tbA = thi - 7;
        float F0  = act ? g_E[j * Nn + 0]  : 0.f, F1  = act ? g_E[j * Nn + 1]  : 0.f;
        float F2  = act ? g_E[j * Nn + 2]  : 0.f, F3  = act ? g_E[j * Nn + 3]  : 0.f;
        float F4  = act ? g_E[j * Nn + 4]  : 0.f, F5  = act ? g_E[j * Nn + 5]  : 0.f;
        float F6  = act ? g_E[j * Nn + 6]  : 0.f, F7  = act ? g_E[j * Nn + 7]  : 0.f;
        float F8  = act ? g_E[j * Nn + 8]  : 0.f, F9  = act ? g_E[j * Nn + 9]  : 0.f;
        float F10 = act ? g_E[j * Nn + 10] : 0.f, F11 = act ? g_E[j * Nn + 11] : 0.f;
        float F12 = act ? g_E[j * Nn + 12] : 0.f, F13 = act ? g_E[j * Nn + 13] : 0.f;
        float F14 = act ? g_E[j * Nn + 14] : 0.f, F15 = act ? g_E[j * Nn + 15] : 0.f;
        float F16 = act ? g_E[j * Nn + 16] : 0.f;

        float rA[8], rB[8], rC[8];
        int mA[8], mB[8], mC[8];
        float ew[8];
#pragma unroll
        for (int u = 0; u < 8; u++) {
            rA[u] = act ? __ldg(inp + (size_t)(tbA + u) * Nn + j) : 0.f;
            mA[u] = __ldg(mkp + tbA + u);
            rB[u] = act ? __ldg(inp + (size_t)(tbA - 8 + u) * Nn + j) : 0.f;
            mB[u] = __ldg(mkp + tbA - 8 + u);
            rC[u] = 0.f; mC[u] = 0;
        }
#pragma unroll
        for (int u = 0; u < 8; u++) ew[u] = __expf(rA[u]);

        float ur = act ? 1.f : 0.f;
        double l2 = 0.0;

        for (int tb = tbA; tb >= tlo; tb -= 8) {
            if (tb - 16 >= tlo) {
                int tp = tb - 16;
#pragma unroll
                for (int u = 0; u < 8; u++) {
                    rC[u] = act ? __ldg(inp + (size_t)(tp + u) * Nn + j) : 0.f;
                    mC[u] = __ldg(mkp + tp + u);
                }
            }
#pragma unroll
            for (int u = 7; u >= 0; u--) {
                float z = ew[u] * ur;
                if (act) wb[cw][u & 1][j] = z;
                __syncwarp();
                float4 v0 = *(const float4*)&wb[cw][u & 1][0];
                float4 v1 = *(const float4*)&wb[cw][u & 1][4];
                float4 v2 = *(const float4*)&wb[cw][u & 1][8];
                float4 v3 = *(const float4*)&wb[cw][u & 1][12];
                float v16 = wb[cw][u & 1][16];
                float a0 = v0.x * F0, a1 = v0.y * F1, a2 = v0.z * F2, a3 = v0.w * F3;
                float a4 = v1.x * F4, a5 = v1.y * F5, a6 = v1.z * F6, a7 = v1.w * F7;
                a0 = fmaf(v2.x, F8, a0);  a1 = fmaf(v2.y, F9, a1);
                a2 = fmaf(v2.z, F10, a2); a3 = fmaf(v2.w, F11, a3);
                a4 = fmaf(v3.x, F12, a4); a5 = fmaf(v3.y, F13, a5);
                a6 = fmaf(v3.z, F14, a6); a7 = fmaf(v3.w, F15, a7);
                a0 = fmaf(v16, F16, a0);
                float cand = ((a0 + a1) + (a2 + a3)) + ((a4 + a5) + (a6 + a7));
                ur = (mA[u] > 0) ? cand : ur;
                if (u == 0) {
                    float sc = v0.x;
                    ur *= __frcp_rn(sc);
                    l2 += (double)__log2f(sc);
                }
            }
#pragma unroll
            for (int u = 0; u < 8; u++) {
                ew[u] = __expf(rB[u]);
                rA[u] = rB[u]; mA[u] = mB[u];
                rB[u] = rC[u]; mB[u] = mC[u];
            }
        }
        if (act) s_vec[cw][j] = ur;
        if (j == 0) s_l2[cw] = l2;
    } else {
        // ===================== NUMERATOR =====================
        float tr_acc = 0.f, em_acc = 0.f;
        int cnt = 0;
        for (int t = j; t < Tn - 1; t += 32) {
            int tg0 = __ldg(tgp + t), tg1 = __ldg(tgp + t + 1);
            int mk0 = __ldg(mkp + t), mk1 = __ldg(mkp + t + 1);
            float ev = __ldg(inp + (size_t)t * Nn + tg0);
            tr_acc = fmaf(s_tr[tg0 * Nn + tg1], (float)mk1, tr_acc);
            em_acc = fmaf(ev, (float)mk0, em_acc);
            cnt += mk0;
        }
#pragma unroll
        for (int off = 16; off; off >>= 1) {
            tr_acc += __shfl_xor_sync(FULL, tr_acc, off);
            em_acc += __shfl_xor_sync(FULL, em_acc, off);
            cnt += __shfl_xor_sync(FULL, cnt, off);
        }
        if (j == 0) {
            int mkL = __ldg(mkp + Tn - 1);
            cnt += mkL;
            int li = cnt - 1; if (li < 0) li = 0;
            int tagL = __ldg(tgp + li);
            float evL = __ldg(inp + (size_t)(Tn - 1) * Nn + tagL) * (float)mkL;
            s_num = tr_acc + em_acc + evL;
        }
    }
    __syncthreads();

    if (wid == 0) {
        // ---- combine: den = s0 + ln2(La1+Lb2+Lb3) + ln(b2.a1)+ln(b3.a2)-ln(sum a2)
        float d1 = act ? s_vec[2][j] * s_vec[0][j] : 0.f;   // b2 . a1
        float d2 = act ? s_vec[3][j] * s_vec[1][j] : 0.f;   // b3 . a2
        float m2 = act ? s_vec[1][j] : 0.f;                  // sum a2
#pragma unroll
        for (int off = 16; off; off >>= 1) {
            d1 += __shfl_xor_sync(FULL, d1, off);
            d2 += __shfl_xor_sync(FULL, d2, off);
            m2 += __shfl_xor_sync(FULL, m2, off);
        }
        if (j == 0) {
            // a2's scale cancels between d2 and m2; only La1, Lb2, Lb3 survive.
            double l2t = s_l2[0] + s_l2[2] + s_l2[3];
            double den = (double)s_s0 + 0.6931471805599453 * l2t
                       + log((double)d1) + log((double)d2) - log((double)m2);
            g_scratch[b] = (float)((double)s_num - den);
            __threadfence();
        }
        int flag = 0;
        if (j == 0) {
            int ticket = atomicAdd(&g_done, 1);
            flag = (ticket == Bn - 1);
        }
        flag = __shfl_sync(FULL, flag, 0);
        if (flag) {
            __threadfence();
            volatile float* gs = g_scratch;
            double acc = 0.0;
#pragma unroll
            for (int k = 0; k < Bn / 32; k++) acc += (double)gs[j + k * 32];
#pragma unroll
            for (int off = 16; off; off >>= 1) acc += __shfl_xor_sync(FULL, acc, off);
            if (j == 0) out[0] = (float)acc;
        }
    }
}

extern "C" void kernel_launch(void* const* d_in, const int* in_sizes, int n_in,
                              void* d_out, int out_size) {
    const float* inputs     = (const float*)d_in[0];
    const int*   tags       = (const int*)d_in[1];
    const float* hiddens    = (const float*)d_in[2];
    const int*   mask       = (const int*)d_in[3];
    const float* p_in       = (const float*)d_in[4];
    const float* p_cross    = (const float*)d_in[5];
    const float* p_out      = (const float*)d_in[6];
    const float* p_to_out   = (const float*)d_in[7];
    const float* p_from_out = (const float*)d_in[8];
    const float* w_attn     = (const float*)d_in[9];
    const float* b_attn     = (const float*)d_in[10];

    k_build<<<1, 1024>>>(hiddens, p_in, p_cross, p_out, p_to_out, p_from_out,
                         w_attn, b_attn);
    k_scan<<<Bn, 160>>>(inputs, tags, mask, (float*)d_out);
}